// round 11
// baseline (speedup 1.0000x reference)
#include <cuda_runtime.h>
#include <cstdint>

#define D 128
#define D4 (D / 4)        // 32 float4 per row
#define MAXN 50000
#define CAP 128           // per-node bucket capacity (mean degree 12)

// Static scratch (allocation-free). NOTE: g_count relies on CUDA's
// zero-initialization of __device__ globals at module load; the gather
// kernel restores it to zero after每 use, keeping the invariant across
// graph replays.
__device__ uint2 g_bucket[(size_t)MAXN * CAP];   // (sender_idx, weight_bits), 51.2 MB
__device__ int   g_count[MAXN];
__device__ float g_y[(size_t)MAXN * D];          // y = x @ W, 25.6 MB

// ---- packed f32x2 FMA (2 MACs per fma-pipe issue) --------------------------
#define FFMA2(acc, a, b) \
    asm("fma.rn.f32x2 %0, %1, %2, %0;" : "+l"(acc) : "l"(a), "l"(b))

// ---------------------------------------------------------------------------
// Kernel A: bucket fill. One thread per edge; spread atomics on counters,
// one 8B record write per edge. Order within a bucket is arbitrary.
// ---------------------------------------------------------------------------
__global__ void fill_kernel(const float* __restrict__ edge_attr,
                            const int* __restrict__ recv,
                            const int* __restrict__ send,
                            int E) {
    int e = blockIdx.x * blockDim.x + threadIdx.x;
    if (e >= E) return;
    int r = recv[e];
    int s = send[e];
    float w = edge_attr[e];
    int slot = atomicAdd(&g_count[r], 1);
    if (slot < CAP)
        g_bucket[(size_t)r * CAP + slot] = make_uint2((unsigned)s, __float_as_uint(w));
}

// ---------------------------------------------------------------------------
// Kernel B: dense GEMM  y = x @ W.  One warp per 4 rows, 8 warps per block.
// x rows staged in warp-private smem PRE-DUPLICATED (float2(v,v)) so the
// per-k splat is one broadcast LDS.64; W row slice loaded directly as
// ulonglong2 (packed operand IS the memory layout -> zero mov overhead).
// 4 rows/warp keeps regs ~48 (8 u64 accums) so ptxas can hoist the LDS
// ahead of the FFMA2 chain without spilling (the R9 8-row variant spilled).
// Inner loop per k: 1 LDG.128 + 4 LDS.64 + 8 FFMA2 = 13 inst.
// ---------------------------------------------------------------------------
__global__ void __launch_bounds__(256)
gemm_kernel(const float* __restrict__ x,
            const float* __restrict__ Wm,
            int N) {
    __shared__ float2 s_c[8][4][D];     // [warp][row][feat] duplicated, 32 KB

    const int lane = threadIdx.x & 31;
    const int wl = (int)(threadIdx.x >> 5);
    const int warp = (int)((blockIdx.x * blockDim.x + threadIdx.x) >> 5);
    const int nwarps = (int)((gridDim.x * blockDim.x) >> 5);

    const float4* x4 = reinterpret_cast<const float4*>(x);
    const ulonglong2* W2 = reinterpret_cast<const ulonglong2*>(Wm);

    const int ngroups = (N + 3) >> 2;

    for (int g = warp; g < ngroups; g += nwarps) {
        int r0 = g << 2;

        // stage 4 rows, elements duplicated for broadcast LDS.64 splat reads
        __syncwarp();
#pragma unroll
        for (int t = 0; t < 4; ++t) {
            int row = r0 + t;
            float4 v = (row < N) ? x4[(unsigned)row * (unsigned)D4 + lane]
                                 : make_float4(0.f, 0.f, 0.f, 0.f);
            float2* dst = &s_c[wl][t][lane * 4];
            dst[0] = make_float2(v.x, v.x);
            dst[1] = make_float2(v.y, v.y);
            dst[2] = make_float2(v.z, v.z);
            dst[3] = make_float2(v.w, v.w);
        }
        __syncwarp();

        unsigned long long aLo[4] = {0, 0, 0, 0};
        unsigned long long aHi[4] = {0, 0, 0, 0};

#pragma unroll 4
        for (int k = 0; k < D; ++k) {
            ulonglong2 w = W2[(unsigned)k * (unsigned)D4 + lane];  // W[k][4L..4L+3]
#pragma unroll
            for (int t = 0; t < 4; ++t) {
                unsigned long long c2 =
                    *reinterpret_cast<const unsigned long long*>(&s_c[wl][t][k]);
                FFMA2(aLo[t], c2, w.x);
                FFMA2(aHi[t], c2, w.y);
            }
        }

        ulonglong2* y2 = reinterpret_cast<ulonglong2*>(g_y);
#pragma unroll
        for (int t = 0; t < 4; ++t) {
            if (r0 + t < N)
                y2[(unsigned)(r0 + t) * (unsigned)D4 + lane] =
                    make_ulonglong2(aLo[t], aHi[t]);
        }
    }
}

// ---------------------------------------------------------------------------
// Kernel C: gather.  out[r] = b + sum_e w_e * y[s_e].  One warp per node.
// At the 307MB L2 roofline (confirmed by ncu: L2 45%, occ 79%). After use,
// lane 0 resets the node's counter to zero so the next graph replay's
// fill_kernel starts from a clean state (replaces the zero kernel).
// ---------------------------------------------------------------------------
__global__ void gather_kernel(const float* __restrict__ bias,
                              float* __restrict__ out,
                              int N) {
    const int lane = threadIdx.x & 31;
    const int node = (int)((blockIdx.x * blockDim.x + threadIdx.x) >> 5);
    const unsigned FULL = 0xffffffffu;
    if (node >= N) return;

    const float4* y4 = reinterpret_cast<const float4*>(g_y);
    float4 acc = reinterpret_cast<const float4*>(bias)[lane];

    int deg = g_count[node];
    if (lane == 0) g_count[node] = 0;   // restore invariant for next replay
    if (deg > CAP) deg = CAP;
    const uint2* bkt = g_bucket + (size_t)node * CAP;

    for (int base = 0; base < deg; base += 32) {
        int m = deg - base; if (m > 32) m = 32;
        uint2 ent = (lane < m) ? bkt[base + lane] : make_uint2(0u, 0u);
        int m1 = m - 1;
        for (int j = 0; j < m; j += 4) {
            int i1 = (j + 1 < m) ? j + 1 : m1;
            int i2 = (j + 2 < m) ? j + 2 : m1;
            int i3 = (j + 3 < m) ? j + 3 : m1;
            unsigned s0 = __shfl_sync(FULL, ent.x, j);
            unsigned s1 = __shfl_sync(FULL, ent.x, i1);
            unsigned s2 = __shfl_sync(FULL, ent.x, i2);
            unsigned s3 = __shfl_sync(FULL, ent.x, i3);
            float w0 = __uint_as_float(__shfl_sync(FULL, ent.y, j));
            float w1 = __uint_as_float(__shfl_sync(FULL, ent.y, i1));
            float w2 = __uint_as_float(__shfl_sync(FULL, ent.y, i2));
            float w3 = __uint_as_float(__shfl_sync(FULL, ent.y, i3));
            if (j + 1 >= m) w1 = 0.f;
            if (j + 2 >= m) w2 = 0.f;
            if (j + 3 >= m) w3 = 0.f;
            // 4 independent 512B row gathers in flight (32-bit indexing)
            float4 v0 = y4[s0 * (unsigned)D4 + lane];
            float4 v1 = y4[s1 * (unsigned)D4 + lane];
            float4 v2 = y4[s2 * (unsigned)D4 + lane];
            float4 v3 = y4[s3 * (unsigned)D4 + lane];
            acc.x = fmaf(w0, v0.x, acc.x); acc.y = fmaf(w0, v0.y, acc.y);
            acc.z = fmaf(w0, v0.z, acc.z); acc.w = fmaf(w0, v0.w, acc.w);
            acc.x = fmaf(w1, v1.x, acc.x); acc.y = fmaf(w1, v1.y, acc.y);
            acc.z = fmaf(w1, v1.z, acc.z); acc.w = fmaf(w1, v1.w, acc.w);
            acc.x = fmaf(w2, v2.x, acc.x); acc.y = fmaf(w2, v2.y, acc.y);
            acc.z = fmaf(w2, v2.z, acc.z); acc.w = fmaf(w2, v2.w, acc.w);
            acc.x = fmaf(w3, v3.x, acc.x); acc.y = fmaf(w3, v3.y, acc.y);
            acc.z = fmaf(w3, v3.z, acc.z); acc.w = fmaf(w3, v3.w, acc.w);
        }
    }

    reinterpret_cast<float4*>(out)[(unsigned)node * (unsigned)D4 + lane] = acc;
}

// ---------------------------------------------------------------------------
// Launch: fill buckets -> y = x@W -> gather (+counter reset)
// (default stream, graph-capturable, allocation-free)
// ---------------------------------------------------------------------------
extern "C" void kernel_launch(void* const* d_in, const int* in_sizes, int n_in,
                              void* d_out, int out_size) {
    const float* x         = (const float*)d_in[0];
    const float* edge_attr = (const float*)d_in[1];
    const float* Wm        = (const float*)d_in[2];
    const float* bias      = (const float*)d_in[3];
    const int*   edge_idx  = (const int*)d_in[4];

    const int N = in_sizes[0] / D;     // 50000
    const int E = in_sizes[1];         // 600000

    fill_kernel<<<(E + 255) / 256, 256>>>(edge_attr,
                                          edge_idx,        // row 0: receivers
                                          edge_idx + E,    // row 1: senders
                                          E);

    int ngroups = (N + 3) / 4;          // one warp per 4 rows
    gemm_kernel<<<(ngroups + 7) / 8, 256>>>(x, Wm, N);

    int warps = N;                      // one warp per node
    gather_kernel<<<(warps + 7) / 8, 256>>>(bias, (float*)d_out, N);
}

// round 12
// speedup vs baseline: 1.1555x; 1.1555x over previous
#include <cuda_runtime.h>
#include <cstdint>

#define D 128
#define D4 (D / 4)        // 32 float4 per row
#define MAXN 50000
#define CAP 128           // per-node bucket capacity (mean degree 12)

// Static scratch (allocation-free). g_count is zero at module load; the
// gather kernel resets each counter after reading it, restoring the
// invariant for every subsequent graph replay (validated in R10).
__device__ uint2 g_bucket[(size_t)MAXN * CAP];   // (sender_idx, weight_bits), 51.2 MB
__device__ int   g_count[MAXN];
__device__ float g_y[(size_t)MAXN * D];          // y = x @ W, 25.6 MB

// ---- packed f32x2 helpers (FFMA2: 2 MACs per fma-pipe issue) ---------------
#define FFMA2(acc, a, b) \
    asm("fma.rn.f32x2 %0, %1, %2, %0;" : "+l"(acc) : "l"(a), "l"(b))
#define PACK2(out, lo, hi) \
    asm("mov.b64 %0, {%1, %2};" : "=l"(out) : "f"(lo), "f"(hi))
#define SPLAT2(out, v) \
    asm("mov.b64 %0, {%1, %1};" : "=l"(out) : "f"(v))

// ---------------------------------------------------------------------------
// Kernel 1: merged fill + GEMM. Independent workloads, complementary
// resources (fill: 6% issue, L2-latency-bound; GEMM: fma/issue-bound).
// Block-modulo split 3:2 interleaves them across all SMs for the whole
// launch, so wall time ~= max(fill, gemm) instead of fill + gemm.
//   bid % 5 <  3 -> fill slice   (grid-stride over edges)
//   bid % 5 >= 3 -> GEMM slice   (grid-stride over 4-row groups; exact R8
//                                 inner loop: LDS.128 + SPLAT2, ~39us proven)
// ---------------------------------------------------------------------------
__global__ void __launch_bounds__(256)
fill_gemm_kernel(const float* __restrict__ edge_attr,
                 const int* __restrict__ recv,
                 const int* __restrict__ send,
                 int E,
                 const float* __restrict__ x,
                 const float* __restrict__ Wm,
                 int N) {
    __shared__ float s_c[8][4][D];      // GEMM staging, 16 KB (fill blocks unused)

    const int bid = blockIdx.x;
    const int mod = bid % 5;

    if (mod < 3) {
        // ---------------- fill slice ----------------
        const int vb = (bid / 5) * 3 + mod;                 // virtual fill block
        const int nvb = (gridDim.x / 5) * 3;                // gridDim multiple of 5
        for (int e = vb * 256 + threadIdx.x; e < E; e += nvb * 256) {
            int r = recv[e];
            int s = send[e];
            float w = edge_attr[e];
            int slot = atomicAdd(&g_count[r], 1);
            if (slot < CAP)
                g_bucket[(size_t)r * CAP + slot] =
                    make_uint2((unsigned)s, __float_as_uint(w));
        }
        return;
    }

    // ---------------- GEMM slice: y = x @ W ----------------
    const int lane = threadIdx.x & 31;
    const int wl = (int)(threadIdx.x >> 5);
    const int vb = (bid / 5) * 2 + (mod - 3);               // virtual gemm block
    const int nvb = (gridDim.x / 5) * 2;
    const int warp = vb * 8 + wl;
    const int nwarps = nvb * 8;

    const float4* x4 = reinterpret_cast<const float4*>(x);
    const float4* W4 = reinterpret_cast<const float4*>(Wm);

    const int ngroups = (N + 3) >> 2;

    for (int g = warp; g < ngroups; g += nwarps) {
        int r0 = g * 4;

        // load 4 input rows (coalesced), stage to smem for broadcast reads
        __syncwarp();
#pragma unroll
        for (int t = 0; t < 4; ++t) {
            float4 v = (r0 + t < N) ? x4[(unsigned)(r0 + t) * (unsigned)D4 + lane]
                                    : make_float4(0.f, 0.f, 0.f, 0.f);
            *reinterpret_cast<float4*>(&s_c[wl][t][lane * 4]) = v;
        }
        __syncwarp();

        unsigned long long aLo[4] = {0, 0, 0, 0};
        unsigned long long aHi[4] = {0, 0, 0, 0};

#pragma unroll 4
        for (int k4 = 0; k4 < D4; ++k4) {
            float4 cc0 = *reinterpret_cast<const float4*>(&s_c[wl][0][k4 * 4]);
            float4 cc1 = *reinterpret_cast<const float4*>(&s_c[wl][1][k4 * 4]);
            float4 cc2 = *reinterpret_cast<const float4*>(&s_c[wl][2][k4 * 4]);
            float4 cc3 = *reinterpret_cast<const float4*>(&s_c[wl][3][k4 * 4]);
#pragma unroll
            for (int kk = 0; kk < 4; ++kk) {
                int k = k4 * 4 + kk;
                float4 w4 = W4[(unsigned)k * (unsigned)D4 + lane];
                unsigned long long wLo, wHi;
                PACK2(wLo, w4.x, w4.y);
                PACK2(wHi, w4.z, w4.w);

                float e0 = (kk == 0) ? cc0.x : (kk == 1) ? cc0.y : (kk == 2) ? cc0.z : cc0.w;
                float e1 = (kk == 0) ? cc1.x : (kk == 1) ? cc1.y : (kk == 2) ? cc1.z : cc1.w;
                float e2 = (kk == 0) ? cc2.x : (kk == 1) ? cc2.y : (kk == 2) ? cc2.z : cc2.w;
                float e3 = (kk == 0) ? cc3.x : (kk == 1) ? cc3.y : (kk == 2) ? cc3.z : cc3.w;

                unsigned long long v0, v1, v2, v3;
                SPLAT2(v0, e0); SPLAT2(v1, e1); SPLAT2(v2, e2); SPLAT2(v3, e3);

                FFMA2(aLo[0], v0, wLo); FFMA2(aHi[0], v0, wHi);
                FFMA2(aLo[1], v1, wLo); FFMA2(aHi[1], v1, wHi);
                FFMA2(aLo[2], v2, wLo); FFMA2(aHi[2], v2, wHi);
                FFMA2(aLo[3], v3, wLo); FFMA2(aHi[3], v3, wHi);
            }
        }

        ulonglong2* y2 = reinterpret_cast<ulonglong2*>(g_y);
#pragma unroll
        for (int t = 0; t < 4; ++t) {
            if (r0 + t < N)
                y2[(unsigned)(r0 + t) * (unsigned)D4 + lane] =
                    make_ulonglong2(aLo[t], aHi[t]);
        }
    }
}

// ---------------------------------------------------------------------------
// Kernel 2: gather.  out[r] = b + sum_e w_e * y[s_e].  One warp per node.
// At the 307MB L2 roofline (ncu: L2 45%, occ 79%, DRAM 14%). Lane 0 resets
// the node's counter after reading it (replaces a zero kernel; validated).
// ---------------------------------------------------------------------------
__global__ void gather_kernel(const float* __restrict__ bias,
                              float* __restrict__ out,
                              int N) {
    const int lane = threadIdx.x & 31;
    const int node = (int)((blockIdx.x * blockDim.x + threadIdx.x) >> 5);
    const unsigned FULL = 0xffffffffu;
    if (node >= N) return;

    const float4* y4 = reinterpret_cast<const float4*>(g_y);
    float4 acc = reinterpret_cast<const float4*>(bias)[lane];

    int deg = g_count[node];
    if (lane == 0) g_count[node] = 0;   // restore invariant for next replay
    if (deg > CAP) deg = CAP;
    const uint2* bkt = g_bucket + (size_t)node * CAP;

    for (int base = 0; base < deg; base += 32) {
        int m = deg - base; if (m > 32) m = 32;
        uint2 ent = (lane < m) ? bkt[base + lane] : make_uint2(0u, 0u);
        int m1 = m - 1;
        for (int j = 0; j < m; j += 4) {
            int i1 = (j + 1 < m) ? j + 1 : m1;
            int i2 = (j + 2 < m) ? j + 2 : m1;
            int i3 = (j + 3 < m) ? j + 3 : m1;
            unsigned s0 = __shfl_sync(FULL, ent.x, j);
            unsigned s1 = __shfl_sync(FULL, ent.x, i1);
            unsigned s2 = __shfl_sync(FULL, ent.x, i2);
            unsigned s3 = __shfl_sync(FULL, ent.x, i3);
            float w0 = __uint_as_float(__shfl_sync(FULL, ent.y, j));
            float w1 = __uint_as_float(__shfl_sync(FULL, ent.y, i1));
            float w2 = __uint_as_float(__shfl_sync(FULL, ent.y, i2));
            float w3 = __uint_as_float(__shfl_sync(FULL, ent.y, i3));
            if (j + 1 >= m) w1 = 0.f;
            if (j + 2 >= m) w2 = 0.f;
            if (j + 3 >= m) w3 = 0.f;
            // 4 independent 512B row gathers in flight (32-bit indexing)
            float4 v0 = y4[s0 * (unsigned)D4 + lane];
            float4 v1 = y4[s1 * (unsigned)D4 + lane];
            float4 v2 = y4[s2 * (unsigned)D4 + lane];
            float4 v3 = y4[s3 * (unsigned)D4 + lane];
            acc.x = fmaf(w0, v0.x, acc.x); acc.y = fmaf(w0, v0.y, acc.y);
            acc.z = fmaf(w0, v0.z, acc.z); acc.w = fmaf(w0, v0.w, acc.w);
            acc.x = fmaf(w1, v1.x, acc.x); acc.y = fmaf(w1, v1.y, acc.y);
            acc.z = fmaf(w1, v1.z, acc.z); acc.w = fmaf(w1, v1.w, acc.w);
            acc.x = fmaf(w2, v2.x, acc.x); acc.y = fmaf(w2, v2.y, acc.y);
            acc.z = fmaf(w2, v2.z, acc.z); acc.w = fmaf(w2, v2.w, acc.w);
            acc.x = fmaf(w3, v3.x, acc.x); acc.y = fmaf(w3, v3.y, acc.y);
            acc.z = fmaf(w3, v3.z, acc.z); acc.w = fmaf(w3, v3.w, acc.w);
        }
    }

    reinterpret_cast<float4*>(out)[(unsigned)node * (unsigned)D4 + lane] = acc;
}

// ---------------------------------------------------------------------------
// Launch: {fill || gemm} (one merged kernel) -> gather (+counter reset)
// (default stream, graph-capturable, allocation-free)
// ---------------------------------------------------------------------------
extern "C" void kernel_launch(void* const* d_in, const int* in_sizes, int n_in,
                              void* d_out, int out_size) {
    const float* x         = (const float*)d_in[0];
    const float* edge_attr = (const float*)d_in[1];
    const float* Wm        = (const float*)d_in[2];
    const float* bias      = (const float*)d_in[3];
    const int*   edge_idx  = (const int*)d_in[4];

    const int N = in_sizes[0] / D;     // 50000
    const int E = in_sizes[1];         // 600000

    // Grid sized so the fill slice (3/5 of blocks) covers E edges in ~1 pass
    // and the GEMM slice (2/5) covers the row groups in ~1 pass; both sides
    // grid-stride, so any remainder is picked up on a second iteration.
    // 3905 = 5 * 781 -> 2343 fill blocks (599,808 threads), 1562 gemm blocks
    // (12,496 warps for 12,500 groups).
    const int grid = 3905;
    fill_gemm_kernel<<<grid, 256>>>(edge_attr,
                                    edge_idx,        // row 0: receivers
                                    edge_idx + E,    // row 1: senders
                                    E, x, Wm, N);

    int warps = N;                      // one warp per node
    gather_kernel<<<(warps + 7) / 8, 256>>>(bias, (float*)d_out, N);
}